// round 12
// baseline (speedup 1.0000x reference)
#include <cuda_runtime.h>
#include <cooperative_groups.h>

namespace cg = cooperative_groups;

// HyperMLP 128->512->512->512->128, per-sample weights streamed from z.
// 2-CTA cluster per sample, DSMEM push exchange (R8 structure).
// ReLU sparsity: ~50% of activations are exactly 0 -> their weight rows are
// never loaded. R12: fully-predicated row body (@p on the ld AND the 4 fmas,
// acc as in/out) — skipped rows cost ~2 live issue slots instead of 11, and
// no zero-movs. Non-volatile asm so ptxas can batch the loads (high MLP).

#define NBATCH 512
#define TOTAL_PARAMS 657024

#define W1_OFF 0          // 128*512
#define B1_OFF 65536      // 512
#define W2_OFF 66048      // 512*512
#define B2_OFF 328192     // 512
#define W3_OFF 328704     // 512*512
#define B3_OFF 590848     // 512
#define W4_OFF 591360     // 512*128
#define B4_OFF 656896     // 128

// If x != 0: wq = *p (streaming), acc += x*wq. Else: nothing (no transaction,
// no FMA). Branch-free; identical arithmetic to adding 0*w.
__device__ __forceinline__ void fma4_if(float4& acc, const float4* p, float x)
{
    asm("{\n\t"
        ".reg .pred q;\n\t"
        ".reg .f32 w0, w1, w2, w3;\n\t"
        "setp.ne.f32 q, %4, 0f00000000;\n\t"
        "@q ld.global.cs.v4.f32 {w0, w1, w2, w3}, [%5];\n\t"
        "@q fma.rn.f32 %0, w0, %4, %0;\n\t"
        "@q fma.rn.f32 %1, w1, %4, %1;\n\t"
        "@q fma.rn.f32 %2, w2, %4, %2;\n\t"
        "@q fma.rn.f32 %3, w3, %4, %3;\n\t"
        "}"
        : "+f"(acc.x), "+f"(acc.y), "+f"(acc.z), "+f"(acc.w)
        : "f"(x), "l"(p));
}

__global__ __launch_bounds__(256, 8) __cluster_dims__(2, 1, 1)
void hypermlp_kernel(const float* __restrict__ z,
                     const float* __restrict__ xq,
                     float* __restrict__ out)
{
    cg::cluster_group cluster = cg::this_cluster();
    const int r    = (int)cluster.block_rank();   // 0 or 1
    const int peer = r ^ 1;
    const int b    = blockIdx.x >> 1;             // sample
    const float* __restrict__ zb = z + (size_t)b * TOTAL_PARAMS;
    const int t = threadIdx.x;                    // 0..255

    __shared__ float xs[2][512];                  // double-buffered activations
    __shared__ float red[1024];                   // 4KB partial-sum buffer

    float (*pxs)[512] = (float (*)[512])cluster.map_shared_rank(xs, peer);

    if (t < 128) xs[0][t] = xq[b * 128 + t];
    __syncthreads();

    const int o = r * 256 + t;                    // this thread's output index

    // ---------------- Layer 1: din=128 (dense input), dout=512 ----------------
    {
        const float4* __restrict__ wv = (const float4*)(zb + W1_OFF); // row=128 f4
        const int lane = t & 63;                  // 64 float4 = 256 outputs
        const int g    = t >> 6;                  // 4 groups x 32 i
        float4 acc = make_float4(0.f, 0.f, 0.f, 0.f);
        #pragma unroll 8
        for (int i = g * 32; i < g * 32 + 32; ++i) {
            const float xi = xs[0][i];
            const float4 wq = __ldcs(&wv[i * 128 + r * 64 + lane]);
            acc.x = fmaf(xi, wq.x, acc.x);
            acc.y = fmaf(xi, wq.y, acc.y);
            acc.z = fmaf(xi, wq.z, acc.z);
            acc.w = fmaf(xi, wq.w, acc.w);
        }
        ((float4*)(red + g * 256))[lane] = acc;
        __syncthreads();
        float v = zb[B1_OFF + o];
        #pragma unroll
        for (int g2 = 0; g2 < 4; ++g2) v += red[g2 * 256 + t];
        v = fmaxf(v, 0.f);
        xs[1][o]  = v;
        pxs[1][o] = v;
        cluster.sync();
    }

    // ---------------- Layers 2 & 3: din=512 (relu-sparse), dout=512 -----------
    {
        const float* p = zb + W2_OFF;
        #pragma unroll 1
        for (int L = 0; L < 2; ++L) {
            const int cur = 1 - L;                // L2 reads buf1, L3 reads buf0
            const int nxt = L;
            const float4* __restrict__ wv = (const float4*)p;
            const float* __restrict__ bias = p + 512 * 512;
            const int lane = t & 63;
            const int g    = t >> 6;              // 4 groups x 128 i
            float4 acc = make_float4(0.f, 0.f, 0.f, 0.f);
            #pragma unroll 8
            for (int i = g * 128; i < g * 128 + 128; ++i) {
                const float xi = xs[cur][i];      // uniform across group
                fma4_if(acc, &wv[i * 128 + r * 64 + lane], xi);
            }
            ((float4*)(red + g * 256))[lane] = acc;
            __syncthreads();
            float v = bias[o];
            #pragma unroll
            for (int g2 = 0; g2 < 4; ++g2) v += red[g2 * 256 + t];
            v = fmaxf(v, 0.f);
            xs[nxt][o]  = v;
            pxs[nxt][o] = v;
            cluster.sync();
            p += 512 * 512 + 512;
        }
    }

    // ---------------- Layer 4: din=512 (relu-sparse), dout=128, no relu -------
    {
        const float4* __restrict__ wv = (const float4*)(zb + W4_OFF); // row=32 f4
        const int lane = t & 15;                  // 16 float4 = 64 outputs
        const int g    = t >> 4;                  // 16 groups x 32 i
        float4 acc = make_float4(0.f, 0.f, 0.f, 0.f);
        #pragma unroll 8
        for (int i = g * 32; i < g * 32 + 32; ++i) {
            const float xi = xs[1][i];
            fma4_if(acc, &wv[i * 32 + r * 16 + lane], xi);
        }
        ((float4*)(red + g * 64))[lane] = acc;    // red as [16][64]
        __syncthreads();
        if (t < 64) {
            float v = zb[B4_OFF + r * 64 + t];
            #pragma unroll
            for (int g2 = 0; g2 < 16; ++g2) v += red[g2 * 64 + t];
            out[b * 128 + r * 64 + t] = v;
        }
    }
}

extern "C" void kernel_launch(void* const* d_in, const int* in_sizes, int n_in,
                              void* d_out, int out_size)
{
    const float* z  = (const float*)d_in[0];
    const float* xq = (const float*)d_in[1];
    if (n_in >= 2 && in_sizes[0] == NBATCH * 128) {
        z  = (const float*)d_in[1];
        xq = (const float*)d_in[0];
    }
    float* out = (float*)d_out;
    hypermlp_kernel<<<NBATCH * 2, 256>>>(z, xq, out);
}

// round 13
// speedup vs baseline: 1.8049x; 1.8049x over previous
#include <cuda_runtime.h>
#include <cooperative_groups.h>

namespace cg = cooperative_groups;

// HyperMLP 128->512->512->512->128, per-sample weights streamed from z.
// 2-CTA cluster per sample, DSMEM push exchange (R8 structure).
// ReLU sparsity: ~50% of activations are exactly 0 -> their weight rows are
// never loaded (predicated ld.global.cs, no branch).
// R13 (vs R11): stale-register predicated load — no per-row zero-movs, no
// volatile. FMAs are plain C (xi==0 rows add 0*stale_finite = +0 exactly),
// so ptxas can rename and front-batch loads (high MLP).

#define NBATCH 512
#define TOTAL_PARAMS 657024

#define W1_OFF 0          // 128*512
#define B1_OFF 65536      // 512
#define W2_OFF 66048      // 512*512
#define B2_OFF 328192     // 512
#define W3_OFF 328704     // 512*512
#define B3_OFF 590848     // 512
#define W4_OFF 591360     // 512*128
#define B4_OFF 656896     // 128

// If x != 0: w = *p (streaming load). Else: w unchanged (stays finite; caller
// initialized it). No branch, no transaction when skipped.
__device__ __forceinline__ void ld_if(float4& w, const float4* p, float x)
{
    asm("{\n\t"
        ".reg .pred q;\n\t"
        "setp.ne.f32 q, %4, 0f00000000;\n\t"
        "@q ld.global.cs.v4.f32 {%0, %1, %2, %3}, [%5];\n\t"
        "}"
        : "+f"(w.x), "+f"(w.y), "+f"(w.z), "+f"(w.w)
        : "f"(x), "l"(p));
}

__global__ __launch_bounds__(256, 8) __cluster_dims__(2, 1, 1)
void hypermlp_kernel(const float* __restrict__ z,
                     const float* __restrict__ xq,
                     float* __restrict__ out)
{
    cg::cluster_group cluster = cg::this_cluster();
    const int r    = (int)cluster.block_rank();   // 0 or 1
    const int peer = r ^ 1;
    const int b    = blockIdx.x >> 1;             // sample
    const float* __restrict__ zb = z + (size_t)b * TOTAL_PARAMS;
    const int t = threadIdx.x;                    // 0..255

    __shared__ float xs[2][512];                  // double-buffered activations
    __shared__ float red[1024];                   // 4KB partial-sum buffer

    float (*pxs)[512] = (float (*)[512])cluster.map_shared_rank(xs, peer);

    if (t < 128) xs[0][t] = xq[b * 128 + t];
    __syncthreads();

    const int o = r * 256 + t;                    // this thread's output index

    // ---------------- Layer 1: din=128 (dense input), dout=512 ----------------
    {
        const float4* __restrict__ wv = (const float4*)(zb + W1_OFF); // row=128 f4
        const int lane = t & 63;                  // 64 float4 = 256 outputs
        const int g    = t >> 6;                  // 4 groups x 32 i
        float4 acc = make_float4(0.f, 0.f, 0.f, 0.f);
        #pragma unroll 8
        for (int i = g * 32; i < g * 32 + 32; ++i) {
            const float xi = xs[0][i];
            const float4 wq = __ldcs(&wv[i * 128 + r * 64 + lane]);
            acc.x = fmaf(xi, wq.x, acc.x);
            acc.y = fmaf(xi, wq.y, acc.y);
            acc.z = fmaf(xi, wq.z, acc.z);
            acc.w = fmaf(xi, wq.w, acc.w);
        }
        ((float4*)(red + g * 256))[lane] = acc;
        __syncthreads();
        float v = zb[B1_OFF + o];
        #pragma unroll
        for (int g2 = 0; g2 < 4; ++g2) v += red[g2 * 256 + t];
        v = fmaxf(v, 0.f);
        xs[1][o]  = v;
        pxs[1][o] = v;
        cluster.sync();
    }

    // ---------------- Layers 2 & 3: din=512 (relu-sparse), dout=512 -----------
    {
        const float* p = zb + W2_OFF;
        #pragma unroll 1
        for (int L = 0; L < 2; ++L) {
            const int cur = 1 - L;                // L2 reads buf1, L3 reads buf0
            const int nxt = L;
            const float4* __restrict__ wv = (const float4*)p;
            const float* __restrict__ bias = p + 512 * 512;
            const int lane = t & 63;
            const int g    = t >> 6;              // 4 groups x 128 i
            float4 acc = make_float4(0.f, 0.f, 0.f, 0.f);
            float4 w   = make_float4(0.f, 0.f, 0.f, 0.f); // stale-safe init
            #pragma unroll 8
            for (int i = g * 128; i < g * 128 + 128; ++i) {
                const float xi = xs[cur][i];      // uniform across group
                ld_if(w, &wv[i * 128 + r * 64 + lane], xi);
                acc.x = fmaf(xi, w.x, acc.x);     // xi==0 -> +0, acc unchanged
                acc.y = fmaf(xi, w.y, acc.y);
                acc.z = fmaf(xi, w.z, acc.z);
                acc.w = fmaf(xi, w.w, acc.w);
            }
            ((float4*)(red + g * 256))[lane] = acc;
            __syncthreads();
            float v = bias[o];
            #pragma unroll
            for (int g2 = 0; g2 < 4; ++g2) v += red[g2 * 256 + t];
            v = fmaxf(v, 0.f);
            xs[nxt][o]  = v;
            pxs[nxt][o] = v;
            cluster.sync();
            p += 512 * 512 + 512;
        }
    }

    // ---------------- Layer 4: din=512 (relu-sparse), dout=128, no relu -------
    {
        const float4* __restrict__ wv = (const float4*)(zb + W4_OFF); // row=32 f4
        const int lane = t & 15;                  // 16 float4 = 64 outputs
        const int g    = t >> 4;                  // 16 groups x 32 i
        float4 acc = make_float4(0.f, 0.f, 0.f, 0.f);
        float4 w   = make_float4(0.f, 0.f, 0.f, 0.f);
        #pragma unroll 8
        for (int i = g * 32; i < g * 32 + 32; ++i) {
            const float xi = xs[1][i];
            ld_if(w, &wv[i * 32 + r * 16 + lane], xi);
            acc.x = fmaf(xi, w.x, acc.x);
            acc.y = fmaf(xi, w.y, acc.y);
            acc.z = fmaf(xi, w.z, acc.z);
            acc.w = fmaf(xi, w.w, acc.w);
        }
        ((float4*)(red + g * 64))[lane] = acc;    // red as [16][64]
        __syncthreads();
        if (t < 64) {
            float v = zb[B4_OFF + r * 64 + t];
            #pragma unroll
            for (int g2 = 0; g2 < 16; ++g2) v += red[g2 * 64 + t];
            out[b * 128 + r * 64 + t] = v;
        }
    }
}

extern "C" void kernel_launch(void* const* d_in, const int* in_sizes, int n_in,
                              void* d_out, int out_size)
{
    const float* z  = (const float*)d_in[0];
    const float* xq = (const float*)d_in[1];
    if (n_in >= 2 && in_sizes[0] == NBATCH * 128) {
        z  = (const float*)d_in[1];
        xq = (const float*)d_in[0];
    }
    float* out = (float*)d_out;
    hypermlp_kernel<<<NBATCH * 2, 256>>>(z, xq, out);
}

// round 15
// speedup vs baseline: 1.9217x; 1.0647x over previous
#include <cuda_runtime.h>
#include <cooperative_groups.h>

namespace cg = cooperative_groups;

// HyperMLP 128->512->512->512->128, per-sample weights streamed from z.
// 2-CTA cluster per sample, DSMEM push exchange (R8 structure).
// ReLU sparsity: ~50% of activations are exactly 0 -> their weight rows are
// not fetched from DRAM. R14: skip via SELECTED ADDRESS, not predication —
// every iteration issues a normal compiler-visible LDG.128, but zero rows
// read a cached dummy line (thread's row-0 address). Loads stay front-
// batched (high MLP); fmaf(0, finite, acc) leaves acc bit-identical.

#define NBATCH 512
#define TOTAL_PARAMS 657024

#define W1_OFF 0          // 128*512
#define B1_OFF 65536      // 512
#define W2_OFF 66048      // 512*512
#define B2_OFF 328192     // 512
#define W3_OFF 328704     // 512*512
#define B3_OFF 590848     // 512
#define W4_OFF 591360     // 512*128
#define B4_OFF 656896     // 128

__global__ __launch_bounds__(256, 8) __cluster_dims__(2, 1, 1)
void hypermlp_kernel(const float* __restrict__ z,
                     const float* __restrict__ xq,
                     float* __restrict__ out)
{
    cg::cluster_group cluster = cg::this_cluster();
    const int r    = (int)cluster.block_rank();   // 0 or 1
    const int peer = r ^ 1;
    const int b    = blockIdx.x >> 1;             // sample
    const float* __restrict__ zb = z + (size_t)b * TOTAL_PARAMS;
    const int t = threadIdx.x;                    // 0..255

    __shared__ float xs[2][512];                  // double-buffered activations
    __shared__ float red[1024];                   // 4KB partial-sum buffer

    float (*pxs)[512] = (float (*)[512])cluster.map_shared_rank(xs, peer);

    if (t < 128) xs[0][t] = xq[b * 128 + t];
    __syncthreads();

    const int o = r * 256 + t;                    // this thread's output index

    // ---------------- Layer 1: din=128 (dense input), dout=512 ----------------
    {
        const float4* __restrict__ wv = (const float4*)(zb + W1_OFF); // row=128 f4
        const int lane = t & 63;                  // 64 float4 = 256 outputs
        const int g    = t >> 6;                  // 4 groups x 32 i
        float4 acc = make_float4(0.f, 0.f, 0.f, 0.f);
        #pragma unroll 8
        for (int i = g * 32; i < g * 32 + 32; ++i) {
            const float xi = xs[0][i];
            const float4 wq = __ldcs(&wv[i * 128 + r * 64 + lane]);
            acc.x = fmaf(xi, wq.x, acc.x);
            acc.y = fmaf(xi, wq.y, acc.y);
            acc.z = fmaf(xi, wq.z, acc.z);
            acc.w = fmaf(xi, wq.w, acc.w);
        }
        ((float4*)(red + g * 256))[lane] = acc;
        __syncthreads();
        float v = zb[B1_OFF + o];
        #pragma unroll
        for (int g2 = 0; g2 < 4; ++g2) v += red[g2 * 256 + t];
        v = fmaxf(v, 0.f);
        xs[1][o]  = v;
        pxs[1][o] = v;
        cluster.sync();
    }

    // ---------------- Layers 2 & 3: din=512 (relu-sparse), dout=512 -----------
    {
        const float* p = zb + W2_OFF;
        #pragma unroll 1
        for (int L = 0; L < 2; ++L) {
            const int cur = 1 - L;                // L2 reads buf1, L3 reads buf0
            const int nxt = L;
            const float4* __restrict__ wv = (const float4*)p;
            const float* __restrict__ bias = p + 512 * 512;
            const int lane = t & 63;
            const int g    = t >> 6;              // 4 groups x 128 i
            const float4* __restrict__ dummy = wv + (r * 64 + lane); // row 0, hot
            float4 acc = make_float4(0.f, 0.f, 0.f, 0.f);
            #pragma unroll 8
            for (int i = g * 128; i < g * 128 + 128; ++i) {
                const float xi = xs[cur][i];      // uniform across group
                const float4* pa = (xi != 0.f) ? (wv + i * 128 + r * 64 + lane)
                                               : dummy;
                const float4 wq = __ldcs(pa);     // plain LDG.128, batchable
                acc.x = fmaf(xi, wq.x, acc.x);    // xi==0 -> +0 exactly
                acc.y = fmaf(xi, wq.y, acc.y);
                acc.z = fmaf(xi, wq.z, acc.z);
                acc.w = fmaf(xi, wq.w, acc.w);
            }
            ((float4*)(red + g * 256))[lane] = acc;
            __syncthreads();
            float v = bias[o];
            #pragma unroll
            for (int g2 = 0; g2 < 4; ++g2) v += red[g2 * 256 + t];
            v = fmaxf(v, 0.f);
            xs[nxt][o]  = v;
            pxs[nxt][o] = v;
            cluster.sync();
            p += 512 * 512 + 512;
        }
    }

    // ---------------- Layer 4: din=512 (relu-sparse), dout=128, no relu -------
    {
        const float4* __restrict__ wv = (const float4*)(zb + W4_OFF); // row=32 f4
        const int lane = t & 15;                  // 16 float4 = 64 outputs
        const int g    = t >> 4;                  // 16 groups x 32 i
        const float4* __restrict__ dummy = wv + (r * 16 + lane);
        float4 acc = make_float4(0.f, 0.f, 0.f, 0.f);
        #pragma unroll 8
        for (int i = g * 32; i < g * 32 + 32; ++i) {
            const float xi = xs[1][i];
            const float4* pa = (xi != 0.f) ? (wv + i * 32 + r * 16 + lane)
                                           : dummy;
            const float4 wq = __ldcs(pa);
            acc.x = fmaf(xi, wq.x, acc.x);
            acc.y = fmaf(xi, wq.y, acc.y);
            acc.z = fmaf(xi, wq.z, acc.z);
            acc.w = fmaf(xi, wq.w, acc.w);
        }
        ((float4*)(red + g * 64))[lane] = acc;    // red as [16][64]
        __syncthreads();
        if (t < 64) {
            float v = zb[B4_OFF + r * 64 + t];
            #pragma unroll
            for (int g2 = 0; g2 < 16; ++g2) v += red[g2 * 64 + t];
            out[b * 128 + r * 64 + t] = v;
        }
    }
}

extern "C" void kernel_launch(void* const* d_in, const int* in_sizes, int n_in,
                              void* d_out, int out_size)
{
    const float* z  = (const float*)d_in[0];
    const float* xq = (const float*)d_in[1];
    if (n_in >= 2 && in_sizes[0] == NBATCH * 128) {
        z  = (const float*)d_in[1];
        xq = (const float*)d_in[0];
    }
    float* out = (float*)d_out;
    hypermlp_kernel<<<NBATCH * 2, 256>>>(z, xq, out);
}